// round 1
// baseline (speedup 1.0000x reference)
#include <cuda_runtime.h>
#include <math.h>

#define D_MODEL 1024
#define N_HEADS 8
#define HEAD_DIM 128
#define T_TOK 8193            // 1 class token + 8192 x rows
#define SS 8224               // padded score stride (multiple of 32)
#define NB_W 128              // blocks for weighted-sum partials
#define CHUNK_W 65            // ceil(8193/128)
#define ATTN_SCALE 0.08838834764831845f   // 1/sqrt(128)

// ---------------- scratch (__device__ globals; no allocation allowed) -------
__device__ float g_q0[D_MODEL];
__device__ float g_u[N_HEADS * D_MODEL];
__device__ float g_c[N_HEADS];
__device__ float g_scores[N_HEADS * SS];
__device__ float g_M[N_HEADS];
__device__ float g_Z[N_HEADS];
__device__ float g_wpart[NB_W * N_HEADS * D_MODEL];
__device__ float g_w[N_HEADS * D_MODEL];
__device__ float g_attn0[D_MODEL];
__device__ float g_out0[D_MODEL];

// ---------------- helpers ---------------------------------------------------
__device__ __forceinline__ float warp_sum(float v) {
#pragma unroll
    for (int o = 16; o; o >>= 1) v += __shfl_xor_sync(0xffffffffu, v, o);
    return v;
}

// y[r] = b[r] + W[r,:] . v     (warp per row, rows = D_MODEL)
__global__ void matvec_warp(const float* __restrict__ W, const float* __restrict__ v,
                            const float* __restrict__ b, float* __restrict__ y) {
    int warp = (blockIdx.x * blockDim.x + threadIdx.x) >> 5;
    int lane = threadIdx.x & 31;
    if (warp >= D_MODEL) return;
    const float* wr = W + (size_t)warp * D_MODEL;
    float acc = 0.f;
#pragma unroll
    for (int i = 0; i < D_MODEL / 32; i++)
        acc += wr[i * 32 + lane] * v[i * 32 + lane];
    acc = warp_sum(acc);
    if (lane == 0) y[warp] = acc + b[warp];
}

// attn0[j] = bv[j] + Wv[j,:] . w[head(j),:]
__global__ void attn0_kernel(const float* __restrict__ Wv, const float* __restrict__ bv) {
    int warp = (blockIdx.x * blockDim.x + threadIdx.x) >> 5;
    int lane = threadIdx.x & 31;
    if (warp >= D_MODEL) return;
    const float* wr = Wv + (size_t)warp * D_MODEL;
    const float* wv = g_w + (size_t)(warp >> 7) * D_MODEL;   // head = j/128
    float acc = 0.f;
#pragma unroll
    for (int i = 0; i < D_MODEL / 32; i++)
        acc += wr[i * 32 + lane] * wv[i * 32 + lane];
    acc = warp_sum(acc);
    if (lane == 0) g_attn0[warp] = acc + bv[warp];
}

// u[h,d] = scale * sum_r Wk[h*128+r, d] * q0[h*128+r]; block 32: c[h]
__global__ void compute_u(const float* __restrict__ Wk, const float* __restrict__ bk) {
    if (blockIdx.x == 32) {   // c[h] = scale * q0_h . bk_h
        int wid = threadIdx.x >> 5, lane = threadIdx.x & 31;
        if (wid < N_HEADS) {
            float acc = 0.f;
#pragma unroll
            for (int i = 0; i < HEAD_DIM / 32; i++) {
                int r = wid * HEAD_DIM + i * 32 + lane;
                acc += g_q0[r] * bk[r];
            }
            acc = warp_sum(acc);
            if (lane == 0) g_c[wid] = acc * ATTN_SCALE;
        }
        return;
    }
    __shared__ float sq[HEAD_DIM];
    int idx = blockIdx.x * 256 + threadIdx.x;   // 32 blocks * 256 = 8192
    int h = idx >> 10;
    if (threadIdx.x < HEAD_DIM) sq[threadIdx.x] = g_q0[h * HEAD_DIM + threadIdx.x];
    __syncthreads();
    const float* wp = Wk + (size_t)h * HEAD_DIM * D_MODEL + (idx & 1023);
    float acc = 0.f;
#pragma unroll 8
    for (int r = 0; r < HEAD_DIM; r++) acc += wp[(size_t)r * D_MODEL] * sq[r];
    g_u[idx] = acc * ATTN_SCALE;
}

// scores[h,t] = u_h . tok_t + c_h  (tiled pass over x; thread = one token)
__global__ void scores_kernel(const float* __restrict__ x, const float* __restrict__ cls) {
    __shared__ float stok[256][33];
    __shared__ float su[N_HEADS][32];
    int t = blockIdx.x * 256 + threadIdx.x;
    float acc[N_HEADS];
#pragma unroll
    for (int h = 0; h < N_HEADS; h++) acc[h] = 0.f;

    for (int dc = 0; dc < D_MODEL; dc += 32) {
        su[threadIdx.x >> 5][threadIdx.x & 31] =
            g_u[(threadIdx.x >> 5) * D_MODEL + dc + (threadIdx.x & 31)];
#pragma unroll
        for (int j = 0; j < 32; j++) {
            int li = j * 256 + threadIdx.x;
            int row = li >> 5;
            int dd = li & 31;
            int gt = blockIdx.x * 256 + row;
            float v = 0.f;
            if (gt < T_TOK) {
                const float* tp = (gt == 0) ? cls : x + (size_t)(gt - 1) * D_MODEL;
                v = tp[dc + dd];
            }
            stok[row][dd] = v;
        }
        __syncthreads();
#pragma unroll
        for (int dd = 0; dd < 32; dd++) {
            float tv = stok[threadIdx.x][dd];
#pragma unroll
            for (int h = 0; h < N_HEADS; h++) acc[h] += tv * su[h][dd];
        }
        __syncthreads();
    }
    if (t < T_TOK) {
#pragma unroll
        for (int h = 0; h < N_HEADS; h++)
            g_scores[h * SS + t] = acc[h] + g_c[h];
    }
}

// per-head: M = max_t score, Z = sum exp(score - M)
__global__ void softmax_reduce() {
    int h = blockIdx.x;
    __shared__ float red[256];
    const float* sc = g_scores + h * SS;
    float m = -1e30f;
    for (int t = threadIdx.x; t < T_TOK; t += 256) m = fmaxf(m, sc[t]);
    red[threadIdx.x] = m;
    __syncthreads();
    for (int s = 128; s; s >>= 1) {
        if (threadIdx.x < s) red[threadIdx.x] = fmaxf(red[threadIdx.x], red[threadIdx.x + s]);
        __syncthreads();
    }
    float M = red[0];
    __syncthreads();
    float z = 0.f;
    for (int t = threadIdx.x; t < T_TOK; t += 256) z += __expf(sc[t] - M);
    red[threadIdx.x] = z;
    __syncthreads();
    for (int s = 128; s; s >>= 1) {
        if (threadIdx.x < s) red[threadIdx.x] += red[threadIdx.x + s];
        __syncthreads();
    }
    if (threadIdx.x == 0) { g_M[h] = M; g_Z[h] = red[0]; }
}

// A[s] = mean_h p[h, s+1]  -> out[7 + s]
__global__ void write_A(float* __restrict__ out, int out_size) {
    int s = blockIdx.x * 256 + threadIdx.x;
    if (s >= 8192) return;
    float a = 0.f;
#pragma unroll
    for (int h = 0; h < N_HEADS; h++)
        a += __expf(g_scores[h * SS + s + 1] - g_M[h]) * (1.0f / g_Z[h]);
    a *= 0.125f;
    if (7 + s < out_size) out[7 + s] = a;
}

// partial weighted token sums: wpart[b,h,d] = sum_{s in chunk b} p[h,s] * tok_s[d]
__global__ void wpart_kernel(const float* __restrict__ x, const float* __restrict__ cls) {
    __shared__ float sp[N_HEADS * (CHUNK_W + 3)];
    const int SPS = CHUNK_W + 3;
    int b = blockIdx.x;
    int s0 = b * CHUNK_W;
    int s1 = min(s0 + CHUNK_W, T_TOK);
    int n = s1 - s0;
    if (n <= 0) n = 0;

    for (int li = threadIdx.x; li < N_HEADS * CHUNK_W; li += 256) {
        int h = li / CHUNK_W;
        int i = li - h * CHUNK_W;
        float p = 0.f;
        if (i < n) p = __expf(g_scores[h * SS + s0 + i] - g_M[h]) / g_Z[h];
        sp[h * SPS + i] = p;
    }
    __syncthreads();

    float4 acc[N_HEADS];
#pragma unroll
    for (int h = 0; h < N_HEADS; h++) acc[h] = make_float4(0.f, 0.f, 0.f, 0.f);
    int d4 = threadIdx.x * 4;

    for (int i = 0; i < n; i++) {
        int gt = s0 + i;
        const float* tp = (gt == 0) ? cls : x + (size_t)(gt - 1) * D_MODEL;
        float4 tv = *reinterpret_cast<const float4*>(tp + d4);
#pragma unroll
        for (int h = 0; h < N_HEADS; h++) {
            float p = sp[h * SPS + i];
            acc[h].x += p * tv.x;
            acc[h].y += p * tv.y;
            acc[h].z += p * tv.z;
            acc[h].w += p * tv.w;
        }
    }
#pragma unroll
    for (int h = 0; h < N_HEADS; h++)
        *reinterpret_cast<float4*>(&g_wpart[(size_t)b * (N_HEADS * D_MODEL) + h * D_MODEL + d4]) = acc[h];
}

__global__ void wreduce() {
    int idx = blockIdx.x * 256 + threadIdx.x;   // 32 * 256 = 8192
    float acc = 0.f;
#pragma unroll 8
    for (int b = 0; b < NB_W; b++) acc += g_wpart[(size_t)b * (N_HEADS * D_MODEL) + idx];
    g_w[idx] = acc;
}

// logits, softmax, argmax -> out[0..6]
__global__ void final_kernel(const float* __restrict__ Wc, const float* __restrict__ bc,
                             float* __restrict__ out, int out_size) {
    __shared__ float slog[2];
    int wid = threadIdx.x >> 5, lane = threadIdx.x & 31;
    if (wid < 2) {
        float acc = 0.f;
#pragma unroll
        for (int i = 0; i < D_MODEL / 32; i++)
            acc += Wc[wid * D_MODEL + i * 32 + lane] * g_out0[i * 32 + lane];
        acc = warp_sum(acc);
        if (lane == 0) slog[wid] = acc + bc[wid];
    }
    __syncthreads();
    if (threadIdx.x == 0 && out_size >= 7) {
        float l0 = slog[0], l1 = slog[1];
        float mx = fmaxf(l0, l1);
        float e0 = __expf(l0 - mx), e1 = __expf(l1 - mx);
        float z = e0 + e1;
        float p0 = e0 / z, p1 = e1 / z;
        float am = (p1 > p0) ? 1.0f : 0.0f;   // argmax, first-index on ties
        out[0] = l0; out[1] = l1;             // top_instance
        out[2] = p0; out[3] = p1;             // Y_prob
        out[4] = am;                          // Y_hat
        out[5] = p0; out[6] = p1;             // y_probs
    }
}

// ---------------- launch -----------------------------------------------------
extern "C" void kernel_launch(void* const* d_in, const int* in_sizes, int n_in,
                              void* d_out, int out_size) {
    const float* x   = (const float*)d_in[0];
    const float* cls = (const float*)d_in[1];
    const float* Wq  = (const float*)d_in[2];
    const float* bq  = (const float*)d_in[3];
    const float* Wk  = (const float*)d_in[4];
    const float* bk  = (const float*)d_in[5];
    const float* Wv  = (const float*)d_in[6];
    const float* bv  = (const float*)d_in[7];
    const float* Wo  = (const float*)d_in[8];
    const float* bo  = (const float*)d_in[9];
    const float* Wc  = (const float*)d_in[10];
    const float* bc  = (const float*)d_in[11];
    float* out = (float*)d_out;

    float* gq0;   cudaGetSymbolAddress((void**)&gq0,   g_q0);
    float* gattn; cudaGetSymbolAddress((void**)&gattn, g_attn0);
    float* gout0; cudaGetSymbolAddress((void**)&gout0, g_out0);

    matvec_warp<<<128, 256>>>(Wq, cls, bq, gq0);               // q0
    compute_u<<<33, 256>>>(Wk, bk);                            // u, c
    scores_kernel<<<33, 256>>>(x, cls);                        // scores (pass 1 over x)
    softmax_reduce<<<8, 256>>>();                              // M, Z per head
    write_A<<<32, 256>>>(out, out_size);                       // A -> out[7..]
    wpart_kernel<<<NB_W, 256>>>(x, cls);                       // weighted sums (pass 2 over x)
    wreduce<<<32, 256>>>();                                    // w
    attn0_kernel<<<128, 256>>>(Wv, bv);                        // attn0
    matvec_warp<<<128, 256>>>(Wo, gattn, bo, gout0);           // out0
    final_kernel<<<1, 64>>>(Wc, bc, out, out_size);            // logits etc.
}

// round 2
// speedup vs baseline: 2.0490x; 2.0490x over previous
#include <cuda_runtime.h>
#include <math.h>

#define D_MODEL 1024
#define N_HEADS 8
#define HEAD_DIM 128
#define T_TOK 8193            // 1 class token + 8192 x rows
#define SS 8224               // padded score stride
#define NB_W 128              // blocks for weighted-sum partials
#define CHUNK_W 65            // ceil(8193/128)
#define SPS (CHUNK_W + 3)
#define S_NBLK 129            // score blocks: 129 * 64 tokens >= 8193
#define ATTN_SCALE 0.08838834764831845f   // 1/sqrt(128)

// ---------------- scratch (__device__ globals) ------------------------------
__device__ float g_q0[D_MODEL];
__device__ float g_u[N_HEADS * D_MODEL];
__device__ float g_c[N_HEADS];
__device__ float g_scores[N_HEADS * SS];
__device__ float g_pM[S_NBLK * N_HEADS];
__device__ float g_pZ[S_NBLK * N_HEADS];
__device__ float g_wpart[NB_W * N_HEADS * D_MODEL];
__device__ float g_w[N_HEADS * D_MODEL];
__device__ float g_attn0[D_MODEL];
__device__ float g_out0[D_MODEL];

// ---------------- helpers ---------------------------------------------------
__device__ __forceinline__ float warp_sum(float v) {
#pragma unroll
    for (int o = 16; o; o >>= 1) v += __shfl_xor_sync(0xffffffffu, v, o);
    return v;
}

// y[r] = b[r] + W[r,:] . v
__global__ void matvec_warp(const float* __restrict__ W, const float* __restrict__ v,
                            const float* __restrict__ b, float* __restrict__ y) {
    int warp = (blockIdx.x * blockDim.x + threadIdx.x) >> 5;
    int lane = threadIdx.x & 31;
    if (warp >= D_MODEL) return;
    const float* wr = W + (size_t)warp * D_MODEL;
    float acc = 0.f;
#pragma unroll
    for (int i = 0; i < D_MODEL / 32; i++)
        acc += wr[i * 32 + lane] * v[i * 32 + lane];
    acc = warp_sum(acc);
    if (lane == 0) y[warp] = acc + b[warp];
}

// attn0[j] = bv[j] + Wv[j,:] . w[head(j),:]
__global__ void attn0_kernel(const float* __restrict__ Wv, const float* __restrict__ bv) {
    int warp = (blockIdx.x * blockDim.x + threadIdx.x) >> 5;
    int lane = threadIdx.x & 31;
    if (warp >= D_MODEL) return;
    const float* wr = Wv + (size_t)warp * D_MODEL;
    const float* wv = g_w + (size_t)(warp >> 7) * D_MODEL;
    float acc = 0.f;
#pragma unroll
    for (int i = 0; i < D_MODEL / 32; i++)
        acc += wr[i * 32 + lane] * wv[i * 32 + lane];
    acc = warp_sum(acc);
    if (lane == 0) g_attn0[warp] = acc + bv[warp];
}

// u[h,d] = scale * sum_r Wk[h*128+r, d] * q0[h*128+r];  block 32: c[h]
__global__ void compute_u(const float* __restrict__ Wk, const float* __restrict__ bk) {
    if (blockIdx.x == 32) {
        int wid = threadIdx.x >> 5, lane = threadIdx.x & 31;
        if (wid < N_HEADS) {
            float acc = 0.f;
#pragma unroll
            for (int i = 0; i < HEAD_DIM / 32; i++) {
                int r = wid * HEAD_DIM + i * 32 + lane;
                acc += g_q0[r] * bk[r];
            }
            acc = warp_sum(acc);
            if (lane == 0) g_c[wid] = acc * ATTN_SCALE;
        }
        return;
    }
    __shared__ float sq[HEAD_DIM];
    int idx = blockIdx.x * 256 + threadIdx.x;
    int h = idx >> 10;
    if (threadIdx.x < HEAD_DIM) sq[threadIdx.x] = g_q0[h * HEAD_DIM + threadIdx.x];
    __syncthreads();
    const float* wp = Wk + (size_t)h * HEAD_DIM * D_MODEL + (idx & 1023);
    float acc = 0.f;
#pragma unroll 16
    for (int r = 0; r < HEAD_DIM; r++) acc += wp[(size_t)r * D_MODEL] * sq[r];
    g_u[idx] = acc * ATTN_SCALE;
}

// ---- scores + block-partial softmax ----------------------------------------
// warp-per-token, 8 tokens per warp, 64 tokens per block, 129 blocks.
__global__ __launch_bounds__(256, 1)
void scores2_kernel(const float* __restrict__ x, const float* __restrict__ cls) {
    __shared__ float4 su4[N_HEADS * 256];     // u as float4: [h*256 + f]
    __shared__ float sc[N_HEADS];
    __shared__ float smz[8 * N_HEADS * 2];    // per-warp (m, z)

    int tid = threadIdx.x;
    const float4* gu4 = (const float4*)g_u;
#pragma unroll
    for (int k = 0; k < 8; k++) su4[k * 256 + tid] = gu4[k * 256 + tid];
    if (tid < N_HEADS) sc[tid] = g_c[tid];
    __syncthreads();

    int w = tid >> 5, lane = tid & 31;
    int t0 = blockIdx.x * 64 + w * 8;

    const float4* rp[8];
    bool val[8];
#pragma unroll
    for (int j = 0; j < 8; j++) {
        int t = t0 + j;
        val[j] = (t < T_TOK);
        const float* p = (t == 0) ? cls : (val[j] ? x + (size_t)(t - 1) * D_MODEL : cls);
        rp[j] = (const float4*)p;
    }

    float acc[8][8];
#pragma unroll
    for (int j = 0; j < 8; j++)
#pragma unroll
        for (int h = 0; h < 8; h++) acc[j][h] = 0.f;

#pragma unroll
    for (int i = 0; i < 8; i++) {
        int f = i * 32 + lane;
        float4 u4[8];
#pragma unroll
        for (int h = 0; h < 8; h++) u4[h] = su4[h * 256 + f];
#pragma unroll
        for (int j = 0; j < 8; j++) {
            float4 tv = rp[j][f];
#pragma unroll
            for (int h = 0; h < 8; h++) {
                acc[j][h] += tv.x * u4[h].x;
                acc[j][h] += tv.y * u4[h].y;
                acc[j][h] += tv.z * u4[h].z;
                acc[j][h] += tv.w * u4[h].w;
            }
        }
    }

    // butterfly-reduce each (token, head) over lanes (all lanes get full sum)
#pragma unroll
    for (int j = 0; j < 8; j++)
#pragma unroll
        for (int h = 0; h < 8; h++) {
            float s = acc[j][h];
#pragma unroll
            for (int o = 16; o; o >>= 1) s += __shfl_xor_sync(0xffffffffu, s, o);
            acc[j][h] = s;
        }

    // lane h (< 8) handles head h: gather its 8 token scores via selects
    float myv[8];
#pragma unroll
    for (int j = 0; j < 8; j++) {
        float v = acc[j][0];
#pragma unroll
        for (int h = 1; h < 8; h++) if (lane == h) v = acc[j][h];
        myv[j] = v;
    }

    if (lane < N_HEADS) {
        float c = sc[lane];
        float m = -3e38f;
#pragma unroll
        for (int j = 0; j < 8; j++) {
            if (val[j]) { myv[j] += c; m = fmaxf(m, myv[j]); }
        }
        float z = 0.f;
#pragma unroll
        for (int j = 0; j < 8; j++) {
            if (val[j]) {
                z += __expf(myv[j] - m);
                g_scores[lane * SS + t0 + j] = myv[j];
            }
        }
        smz[(w * N_HEADS + lane) * 2 + 0] = m;
        smz[(w * N_HEADS + lane) * 2 + 1] = z;
    }
    __syncthreads();

    if (tid < N_HEADS) {
        int h = tid;
        float M = -3e38f, Z = 0.f;
#pragma unroll
        for (int ww = 0; ww < 8; ww++) {
            float m = smz[(ww * N_HEADS + h) * 2 + 0];
            float z = smz[(ww * N_HEADS + h) * 2 + 1];
            float nm = fmaxf(M, m);
            Z = Z * __expf(M - nm) + z * __expf(m - nm);
            M = nm;
        }
        g_pM[blockIdx.x * N_HEADS + h] = M;
        g_pZ[blockIdx.x * N_HEADS + h] = Z;
    }
}

// ---- weighted token sums + A output (fused softmax finalize) ---------------
__global__ __launch_bounds__(256)
void wpart2_kernel(const float* __restrict__ x, const float* __restrict__ cls,
                   float* __restrict__ out, int out_size) {
    __shared__ float sM[N_HEADS], sZi[N_HEADS];
    __shared__ float sp[N_HEADS * SPS];

    int tid = threadIdx.x;
    int w = tid >> 5, lane = tid & 31;

    // merge the 129 block partials: warp w handles head w
    {
        int h = w;
        float m = -3e38f, z = 0.f;
        for (int b = lane; b < S_NBLK; b += 32) {
            float bm = g_pM[b * N_HEADS + h];
            float bz = g_pZ[b * N_HEADS + h];
            float nm = fmaxf(m, bm);
            z = z * __expf(m - nm) + bz * __expf(bm - nm);
            m = nm;
        }
#pragma unroll
        for (int o = 16; o; o >>= 1) {
            float om = __shfl_xor_sync(0xffffffffu, m, o);
            float oz = __shfl_xor_sync(0xffffffffu, z, o);
            float nm = fmaxf(m, om);
            z = z * __expf(m - nm) + oz * __expf(om - nm);
            m = nm;
        }
        if (lane == 0) { sM[h] = m; sZi[h] = 1.0f / z; }
    }
    __syncthreads();

    int b = blockIdx.x;
    int s0 = b * CHUNK_W;
    int s1 = min(s0 + CHUNK_W, T_TOK);
    int n = s1 - s0;
    if (n < 0) n = 0;

    for (int li = tid; li < N_HEADS * CHUNK_W; li += 256) {
        int h = li / CHUNK_W;
        int i = li - h * CHUNK_W;
        float p = 0.f;
        if (i < n) p = __expf(g_scores[h * SS + s0 + i] - sM[h]) * sZi[h];
        sp[h * SPS + i] = p;
    }
    __syncthreads();

    // A output: A[gt-1] = mean_h p[h, gt] for gt >= 1
    for (int i = tid; i < n; i += 256) {
        int gt = s0 + i;
        if (gt > 0) {
            float a = 0.f;
#pragma unroll
            for (int h = 0; h < N_HEADS; h++) a += sp[h * SPS + i];
            a *= 0.125f;
            int oi = 7 + gt - 1;
            if (oi < out_size) out[oi] = a;
        }
    }

    float4 acc[N_HEADS];
#pragma unroll
    for (int h = 0; h < N_HEADS; h++) acc[h] = make_float4(0.f, 0.f, 0.f, 0.f);
    int d4 = tid * 4;

#pragma unroll 4
    for (int i = 0; i < n; i++) {
        int gt = s0 + i;
        const float* tp = (gt == 0) ? cls : x + (size_t)(gt - 1) * D_MODEL;
        float4 tv = *reinterpret_cast<const float4*>(tp + d4);
#pragma unroll
        for (int h = 0; h < N_HEADS; h++) {
            float p = sp[h * SPS + i];
            acc[h].x += p * tv.x;
            acc[h].y += p * tv.y;
            acc[h].z += p * tv.z;
            acc[h].w += p * tv.w;
        }
    }
#pragma unroll
    for (int h = 0; h < N_HEADS; h++)
        *reinterpret_cast<float4*>(&g_wpart[(size_t)b * (N_HEADS * D_MODEL) + h * D_MODEL + d4]) = acc[h];
}

__global__ void wreduce() {
    int idx = blockIdx.x * 256 + threadIdx.x;
    float acc = 0.f;
#pragma unroll 8
    for (int b = 0; b < NB_W; b++) acc += g_wpart[(size_t)b * (N_HEADS * D_MODEL) + idx];
    g_w[idx] = acc;
}

// logits, softmax, argmax -> out[0..6]
__global__ void final_kernel(const float* __restrict__ Wc, const float* __restrict__ bc,
                             float* __restrict__ out, int out_size) {
    __shared__ float slog[2];
    int wid = threadIdx.x >> 5, lane = threadIdx.x & 31;
    if (wid < 2) {
        float acc = 0.f;
#pragma unroll
        for (int i = 0; i < D_MODEL / 32; i++)
            acc += Wc[wid * D_MODEL + i * 32 + lane] * g_out0[i * 32 + lane];
        acc = warp_sum(acc);
        if (lane == 0) slog[wid] = acc + bc[wid];
    }
    __syncthreads();
    if (threadIdx.x == 0 && out_size >= 7) {
        float l0 = slog[0], l1 = slog[1];
        float mx = fmaxf(l0, l1);
        float e0 = __expf(l0 - mx), e1 = __expf(l1 - mx);
        float z = e0 + e1;
        float p0 = e0 / z, p1 = e1 / z;
        float am = (p1 > p0) ? 1.0f : 0.0f;
        out[0] = l0; out[1] = l1;
        out[2] = p0; out[3] = p1;
        out[4] = am;
        out[5] = p0; out[6] = p1;
    }
}

// ---------------- launch -----------------------------------------------------
extern "C" void kernel_launch(void* const* d_in, const int* in_sizes, int n_in,
                              void* d_out, int out_size) {
    const float* x   = (const float*)d_in[0];
    const float* cls = (const float*)d_in[1];
    const float* Wq  = (const float*)d_in[2];
    const float* bq  = (const float*)d_in[3];
    const float* Wk  = (const float*)d_in[4];
    const float* bk  = (const float*)d_in[5];
    const float* Wv  = (const float*)d_in[6];
    const float* bv  = (const float*)d_in[7];
    const float* Wo  = (const float*)d_in[8];
    const float* bo  = (const float*)d_in[9];
    const float* Wc  = (const float*)d_in[10];
    const float* bc  = (const float*)d_in[11];
    float* out = (float*)d_out;

    float* gq0;   cudaGetSymbolAddress((void**)&gq0,   g_q0);
    float* gattn; cudaGetSymbolAddress((void**)&gattn, g_attn0);
    float* gout0; cudaGetSymbolAddress((void**)&gout0, g_out0);

    matvec_warp<<<128, 256>>>(Wq, cls, bq, gq0);        // q0
    compute_u<<<33, 256>>>(Wk, bk);                     // u, c
    scores2_kernel<<<S_NBLK, 256>>>(x, cls);            // scores + block partials
    wpart2_kernel<<<NB_W, 256>>>(x, cls, out, out_size);// merge softmax, A, weighted sums
    wreduce<<<32, 256>>>();                             // w
    attn0_kernel<<<128, 256>>>(Wv, bv);                 // attn0
    matvec_warp<<<128, 256>>>(Wo, gattn, bo, gout0);    // out0
    final_kernel<<<1, 64>>>(Wc, bc, out, out_size);     // logits etc.
}

// round 5
// speedup vs baseline: 2.1805x; 1.0642x over previous
#include <cuda_runtime.h>
#include <math.h>

#define D_MODEL 1024
#define N_HEADS 8
#define HEAD_DIM 128
#define T_TOK 8193            // 1 class token + 8192 x rows
#define SS 8224               // padded score stride
#define S_NBLK 129            // 129 blocks * 64 tokens >= 8193
#define ATTN_SCALE 0.08838834764831845f   // 1/sqrt(128)

// ---------------- scratch (__device__ globals) ------------------------------
__device__ float g_q0[D_MODEL];
__device__ float g_u[N_HEADS * D_MODEL];
__device__ float g_c[N_HEADS];
__device__ float g_scores[N_HEADS * SS];
__device__ float g_pM[S_NBLK * N_HEADS];
__device__ float g_pZ[S_NBLK * N_HEADS];
__device__ float g_wpart[S_NBLK * N_HEADS * D_MODEL];
__device__ float g_w[N_HEADS * D_MODEL];
__device__ float g_attn0[D_MODEL];
__device__ float g_out0[D_MODEL];

// ---------------- helpers ---------------------------------------------------
__device__ __forceinline__ float warp_sum(float v) {
#pragma unroll
    for (int o = 16; o; o >>= 1) v += __shfl_xor_sync(0xffffffffu, v, o);
    return v;
}

// y[r] = b[r] + W[r,:] . v
__global__ void matvec_warp(const float* __restrict__ W, const float* __restrict__ v,
                            const float* __restrict__ b, float* __restrict__ y) {
    int warp = (blockIdx.x * blockDim.x + threadIdx.x) >> 5;
    int lane = threadIdx.x & 31;
    if (warp >= D_MODEL) return;
    const float* wr = W + (size_t)warp * D_MODEL;
    float acc = 0.f;
#pragma unroll
    for (int i = 0; i < D_MODEL / 32; i++)
        acc += wr[i * 32 + lane] * v[i * 32 + lane];
    acc = warp_sum(acc);
    if (lane == 0) y[warp] = acc + b[warp];
}

// attn0[j] = bv[j] + Wv[j,:] . w[head(j),:]
__global__ void attn0_kernel(const float* __restrict__ Wv, const float* __restrict__ bv) {
    int warp = (blockIdx.x * blockDim.x + threadIdx.x) >> 5;
    int lane = threadIdx.x & 31;
    if (warp >= D_MODEL) return;
    const float* wr = Wv + (size_t)warp * D_MODEL;
    const float* wv = g_w + (size_t)(warp >> 7) * D_MODEL;
    float acc = 0.f;
#pragma unroll
    for (int i = 0; i < D_MODEL / 32; i++)
        acc += wr[i * 32 + lane] * wv[i * 32 + lane];
    acc = warp_sum(acc);
    if (lane == 0) g_attn0[warp] = acc + bv[warp];
}

// u[h,d] = scale * sum_r Wk[h*128+r, d] * q0[h*128+r];  block 32: c[h]
__global__ void compute_u(const float* __restrict__ Wk, const float* __restrict__ bk) {
    if (blockIdx.x == 32) {
        int wid = threadIdx.x >> 5, lane = threadIdx.x & 31;
        if (wid < N_HEADS) {
            float acc = 0.f;
#pragma unroll
            for (int i = 0; i < HEAD_DIM / 32; i++) {
                int r = wid * HEAD_DIM + i * 32 + lane;
                acc += g_q0[r] * bk[r];
            }
            acc = warp_sum(acc);
            if (lane == 0) g_c[wid] = acc * ATTN_SCALE;
        }
        return;
    }
    __shared__ float sq[HEAD_DIM];
    int idx = blockIdx.x * 256 + threadIdx.x;
    int h = idx >> 10;
    if (threadIdx.x < HEAD_DIM) sq[threadIdx.x] = g_q0[h * HEAD_DIM + threadIdx.x];
    __syncthreads();
    const float* wp = Wk + (size_t)h * HEAD_DIM * D_MODEL + (idx & 1023);
    float acc = 0.f;
#pragma unroll 16
    for (int r = 0; r < HEAD_DIM; r++) acc += wp[(size_t)r * D_MODEL] * sq[r];
    g_u[idx] = acc * ATTN_SCALE;
}

// ---- fused: scores + block softmax partials + weighted token partial sums --
// 64 tokens per block, 129 blocks. x is read from DRAM once (stage-2 re-reads
// the block's own tile out of L1/L2).
__global__ __launch_bounds__(256, 1)
void fused_kernel(const float* __restrict__ x, const float* __restrict__ cls) {
    __shared__ float4 su4[N_HEADS * 256];     // u as float4
    __shared__ float sc[N_HEADS];
    __shared__ float ss[N_HEADS][64];         // block scores
    __shared__ float sp[N_HEADS][64];         // e^{s - m_b}

    int tid = threadIdx.x;
    const float4* gu4 = (const float4*)g_u;
#pragma unroll
    for (int k = 0; k < 8; k++) su4[k * 256 + tid] = gu4[k * 256 + tid];
    if (tid < N_HEADS) sc[tid] = g_c[tid];
    __syncthreads();

    int w = tid >> 5, lane = tid & 31;
    int t0 = blockIdx.x * 64 + w * 8;

    // ---- stage 1: scores, warp-per-8-tokens ----
    const float4* rp[8];
    bool val[8];
#pragma unroll
    for (int j = 0; j < 8; j++) {
        int t = t0 + j;
        val[j] = (t < T_TOK);
        const float* p = (t == 0) ? cls : (val[j] ? x + (size_t)(t - 1) * D_MODEL : cls);
        rp[j] = (const float4*)p;
    }

    float acc[8][8];
#pragma unroll
    for (int j = 0; j < 8; j++)
#pragma unroll
        for (int h = 0; h < 8; h++) acc[j][h] = 0.f;

#pragma unroll
    for (int i = 0; i < 8; i++) {
        int f = i * 32 + lane;
        float4 u4[8];
#pragma unroll
        for (int h = 0; h < 8; h++) u4[h] = su4[h * 256 + f];
#pragma unroll
        for (int j = 0; j < 8; j++) {
            float4 tv = rp[j][f];
#pragma unroll
            for (int h = 0; h < 8; h++) {
                acc[j][h] += tv.x * u4[h].x;
                acc[j][h] += tv.y * u4[h].y;
                acc[j][h] += tv.z * u4[h].z;
                acc[j][h] += tv.w * u4[h].w;
            }
        }
    }

#pragma unroll
    for (int j = 0; j < 8; j++)
#pragma unroll
        for (int h = 0; h < 8; h++) {
            float s = acc[j][h];
#pragma unroll
            for (int o = 16; o; o >>= 1) s += __shfl_xor_sync(0xffffffffu, s, o);
            acc[j][h] = s;
        }

    // lane h (< 8) owns head h
    float myv[8];
#pragma unroll
    for (int j = 0; j < 8; j++) {
        float v = acc[j][0];
#pragma unroll
        for (int h = 1; h < 8; h++) if (lane == h) v = acc[j][h];
        myv[j] = v;
    }

    if (lane < N_HEADS) {
        float c = sc[lane];
#pragma unroll
        for (int j = 0; j < 8; j++) {
            float s = val[j] ? (myv[j] + c) : -3e38f;
            ss[lane][w * 8 + j] = s;
            if (val[j]) g_scores[lane * SS + t0 + j] = s;
        }
    }
    __syncthreads();

    // ---- block softmax partials: warp h handles head h ----
    if (w < N_HEADS) {
        int h = w;
        float v0 = ss[h][lane], v1 = ss[h][lane + 32];
        float m = fmaxf(v0, v1);
#pragma unroll
        for (int o = 16; o; o >>= 1) m = fmaxf(m, __shfl_xor_sync(0xffffffffu, m, o));
        float e0 = __expf(v0 - m), e1 = __expf(v1 - m);
        sp[h][lane] = e0;
        sp[h][lane + 32] = e1;
        float z = warp_sum(e0 + e1);
        if (lane == 0) {
            g_pM[blockIdx.x * N_HEADS + h] = m;
            g_pZ[blockIdx.x * N_HEADS + h] = z;
        }
    }
    __syncthreads();

    // ---- stage 2: locally-normalized weighted token sums (tile from L1/L2) --
    float4 wacc[N_HEADS];
#pragma unroll
    for (int h = 0; h < N_HEADS; h++) wacc[h] = make_float4(0.f, 0.f, 0.f, 0.f);
    int d4 = tid * 4;
    int base = blockIdx.x * 64;
    int n = min(64, T_TOK - base);

#pragma unroll 4
    for (int i = 0; i < n; i++) {
        int gt = base + i;
        const float* tp = (gt == 0) ? cls : x + (size_t)(gt - 1) * D_MODEL;
        float4 tv = *reinterpret_cast<const float4*>(tp + d4);
#pragma unroll
        for (int h = 0; h < N_HEADS; h++) {
            float p = sp[h][i];
            wacc[h].x += p * tv.x;
            wacc[h].y += p * tv.y;
            wacc[h].z += p * tv.z;
            wacc[h].w += p * tv.w;
        }
    }
#pragma unroll
    for (int h = 0; h < N_HEADS; h++)
        *reinterpret_cast<float4*>(
            &g_wpart[(size_t)blockIdx.x * (N_HEADS * D_MODEL) + h * D_MODEL + d4]) = wacc[h];
}

// ---- finalize: blocks 0..31 merge w partials; blocks 32..63 write A --------
__global__ __launch_bounds__(256)
void finalize_kernel(float* __restrict__ out, int out_size) {
    __shared__ float sM[N_HEADS], sZi[N_HEADS];
    __shared__ float sf[S_NBLK];

    int tid = threadIdx.x;
    int w = tid >> 5, lane = tid & 31;

    // global (M, Z) per head: warp h merges the 129 block partials
    if (w < N_HEADS) {
        int h = w;
        float m = -3e38f, z = 0.f;
        for (int b = lane; b < S_NBLK; b += 32) {
            float bm = g_pM[b * N_HEADS + h];
            float bz = g_pZ[b * N_HEADS + h];
            float nm = fmaxf(m, bm);
            z = z * __expf(m - nm) + bz * __expf(bm - nm);
            m = nm;
        }
#pragma unroll
        for (int o = 16; o; o >>= 1) {
            float om = __shfl_xor_sync(0xffffffffu, m, o);
            float oz = __shfl_xor_sync(0xffffffffu, z, o);
            float nm = fmaxf(m, om);
            z = z * __expf(m - nm) + oz * __expf(om - nm);
            m = nm;
        }
        if (lane == 0) { sM[h] = m; sZi[h] = 1.0f / z; }
    }
    __syncthreads();

    if (blockIdx.x < 32) {
        // w[idx] = sum_b wpart[b][idx] * e^{m_b - M} / Z ; h is constant per block
        int idx = blockIdx.x * 256 + tid;
        int h = idx >> 10;
        for (int b = tid; b < S_NBLK; b += 256)
            sf[b] = __expf(g_pM[b * N_HEADS + h] - sM[h]) * sZi[h];
        __syncthreads();
        float acc = 0.f;
        for (int b = 0; b < S_NBLK; b++)
            acc += g_wpart[(size_t)b * (N_HEADS * D_MODEL) + idx] * sf[b];
        g_w[idx] = acc;
    } else {
        // A[s] = mean_h p[h, s+1]
        int s = (blockIdx.x - 32) * 256 + tid;   // 0..8191
        float a = 0.f;
#pragma unroll
        for (int h = 0; h < N_HEADS; h++)
            a += __expf(g_scores[h * SS + s + 1] - sM[h]) * sZi[h];
        a *= 0.125f;
        int oi = 7 + s;
        if (oi < out_size) out[oi] = a;
    }
}

// logits, softmax, argmax -> out[0..6]
__global__ void final_kernel(const float* __restrict__ Wc, const float* __restrict__ bc,
                             float* __restrict__ out, int out_size) {
    __shared__ float slog[2];
    int wid = threadIdx.x >> 5, lane = threadIdx.x & 31;
    if (wid < 2) {
        float acc = 0.f;
#pragma unroll
        for (int i = 0; i < D_MODEL / 32; i++)
            acc += Wc[wid * D_MODEL + i * 32 + lane] * g_out0[i * 32 + lane];
        acc = warp_sum(acc);
        if (lane == 0) slog[wid] = acc + bc[wid];
    }
    __syncthreads();
    if (threadIdx.x == 0 && out_size >= 7) {
        float l0 = slog[0], l1 = slog[1];
        float mx = fmaxf(l0, l1);
        float e0 = __expf(l0 - mx), e1 = __expf(l1 - mx);
        float z = e0 + e1;
        float p0 = e0 / z, p1 = e1 / z;
        float am = (p1 > p0) ? 1.0f : 0.0f;
        out[0] = l0; out[1] = l1;
        out[2] = p0; out[3] = p1;
        out[4] = am;
        out[5] = p0; out[6] = p1;
    }
}

// ---------------- launch -----------------------------------------------------
extern "C" void kernel_launch(void* const* d_in, const int* in_sizes, int n_in,
                              void* d_out, int out_size) {
    const float* x   = (const float*)d_in[0];
    const float* cls = (const float*)d_in[1];
    const float* Wq  = (const float*)d_in[2];
    const float* bq  = (const float*)d_in[3];
    const float* Wk  = (const float*)d_in[4];
    const float* bk  = (const float*)d_in[5];
    const float* Wv  = (const float*)d_in[6];
    const float* bv  = (const float*)d_in[7];
    const float* Wo  = (const float*)d_in[8];
    const float* bo  = (const float*)d_in[9];
    const float* Wc  = (const float*)d_in[10];
    const float* bc  = (const float*)d_in[11];
    float* out = (float*)d_out;

    float* gq0;   cudaGetSymbolAddress((void**)&gq0,   g_q0);
    float* gattn; cudaGetSymbolAddress((void**)&gattn, g_attn0);
    float* gout0; cudaGetSymbolAddress((void**)&gout0, g_out0);

    matvec_warp<<<128, 256>>>(Wq, cls, bq, gq0);        // q0
    compute_u<<<33, 256>>>(Wk, bk);                     // u, c
    fused_kernel<<<S_NBLK, 256>>>(x, cls);              // scores + partials (1 x pass)
    finalize_kernel<<<64, 256>>>(out, out_size);        // merge -> w, write A
    attn0_kernel<<<128, 256>>>(Wv, bv);                 // attn0
    matvec_warp<<<128, 256>>>(Wo, gattn, bo, gout0);    // out0
    final_kernel<<<1, 64>>>(Wc, bc, out, out_size);     // logits etc.
}